// round 14
// baseline (speedup 1.0000x reference)
#include <cuda_runtime.h>
#include <math.h>
#include <stdint.h>

#define KCODES 1024
#define DDIM   64
#define NBLOCKS 256       // 32768 rows / 128 rows per block
#define CTILES  16        // 1024 codes / 64 codes per tile

// ---------------- device scratch (no allocation allowed) ----------------
// g_hist, g_gram, g_done rely on the zero-invariant: zero at module load,
// re-zeroed by finalize at the end of every run (graph-replay safe).
__device__ float g_en2[KCODES];
__device__ int   g_hist[KCODES];
__device__ float g_usedp[16];
__device__ float g_pcommit[NBLOCKS];
__device__ float g_pent[NBLOCKS];
__device__ float g_gram[4096];
__device__ float g_bq[KCODES * 128];   // B quads: [code][kk][q][4] = (hi_k, hi_k+4, lo_k, lo_k+4), k=kk*8+q
__device__ int   g_done;

// ---------------- helpers ----------------
__device__ __forceinline__ float to_tf32(float v) {
    float r;
    asm("cvt.rna.tf32.f32 %0, %1;" : "=f"(r) : "f"(v));
    return r;
}

// D += A(row-major m16k8, tf32) * B(col-major k8n8, tf32), fp32 accum
__device__ __forceinline__ void mma_tf32(float& d0, float& d1, float& d2, float& d3,
                                         const uint32_t a[4], uint32_t b0, uint32_t b1) {
    asm("mma.sync.aligned.m16n8k8.row.col.f32.tf32.tf32.f32 "
        "{%0,%1,%2,%3}, {%4,%5,%6,%7}, {%8,%9}, {%0,%1,%2,%3};"
        : "+f"(d0), "+f"(d1), "+f"(d2), "+f"(d3)
        : "r"(a[0]), "r"(a[1]), "r"(a[2]), "r"(a[3]), "r"(b0), "r"(b1));
}

// batched online-softmax update for a pair of new logits
#define UPD2(mv, Zv, Sv, biv, av0, av1, col0) do {                            \
    float _q = fmaxf((av0), (av1));                                           \
    if (_q > (mv)) {                                                          \
        float _scl = __expf((mv) - _q);                                       \
        (Zv) *= _scl; (Sv) *= _scl;                                           \
        (mv) = _q;                                                            \
        (biv) = ((av0) >= (av1)) ? (col0) : (col0) + 1;                       \
    }                                                                         \
    float _p0 = __expf((av0) - (mv));                                         \
    float _p1 = __expf((av1) - (mv));                                         \
    (Zv) += _p0 + _p1;                                                        \
    (Sv) = fmaf((av0), _p0, fmaf((av1), _p1, (Sv)));                          \
} while (0)

#define MERGE(mv, Zv, Sv, biv, m2, Z2, S2, b2) do {                           \
    float _mm = fmaxf((mv), (m2));                                            \
    float _sA = __expf((mv) - _mm);                                           \
    float _sB = __expf((m2) - _mm);                                           \
    float _Zn = (Zv) * _sA + (Z2) * _sB;                                      \
    float _Sn = (Sv) * _sA + (S2) * _sB;                                      \
    if ((m2) > (mv) || ((m2) == (mv) && (b2) < (biv))) (biv) = (b2);          \
    (mv) = _mm; (Zv) = _Zn; (Sv) = _Sn; } while (0)

// ---------------- aux: en2 + used + B-quad precompute + ortho Gram partial ----------------
__global__ __launch_bounds__(256, 4)
void aux_kernel(const float* __restrict__ emb, const float* __restrict__ cc) {
    __shared__ float nt[64 * 68];
    __shared__ float scl[64];
    int tid = threadIdx.x;
    int k0 = blockIdx.x * 64;

    // load 64 codes x 64 dims (raw)
#pragma unroll
    for (int i = 0; i < 4; i++) {
        int v = tid + 256 * i;
        int k = v >> 4, c4 = v & 15;
        *(float4*)(nt + k * 68 + c4 * 4) = ((const float4*)emb)[(size_t)(k0 + k) * 16 + c4];
    }
    __syncthreads();

    if (tid < 64) {
        float s = 0.f;
        const float* r = nt + tid * 68;
#pragma unroll 8
        for (int d = 0; d < 64; d++) s = fmaf(r[d], r[d], s);
        g_en2[k0 + tid] = s;
        float msk = (cc[k0 + tid] >= 1.f) ? 1.f : 0.f;
        scl[tid] = msk / fmaxf(sqrtf(s), 1e-12f);
    }
    __syncthreads();

    if (tid == 0) {
        float u = 0.f;
        for (int i = 0; i < 64; i++) u += (scl[i] > 0.f) ? 1.f : 0.f;
        g_usedp[blockIdx.x] = u;
    }

    // B-quad precompute from RAW rows (before in-place scaling):
    // item v in [0,512): codeLocal = v>>3, kk = v&7 -> 4 quads
#pragma unroll
    for (int i = 0; i < 2; i++) {
        int v = tid + 256 * i;
        int cl = v >> 3, kk = v & 7;
        const float* rp = nt + cl * 68 + kk * 8;
        float4 t0 = *(const float4*)(rp);
        float4 t1 = *(const float4*)(rp + 4);
        float e[8] = { t0.x, t0.y, t0.z, t0.w, t1.x, t1.y, t1.z, t1.w };
        float hi[8], lo[8];
#pragma unroll
        for (int j = 0; j < 8; j++) { hi[j] = to_tf32(e[j]); lo[j] = to_tf32(e[j] - hi[j]); }
        float* base = g_bq + (size_t)(k0 + cl) * 128 + kk * 16;
#pragma unroll
        for (int q = 0; q < 4; q++)
            *(float4*)(base + q * 4) = make_float4(hi[q], hi[q + 4], lo[q], lo[q + 4]);
    }
    __syncthreads();

    // scale rows to masked-normalized (in place)
#pragma unroll
    for (int i = 0; i < 4; i++) {
        int v = tid + 256 * i;
        int k = v >> 4, c4 = v & 15;
        float4* p = (float4*)(nt + k * 68 + c4 * 4);
        float4 t = *p;
        float s = scl[k];
        t.x *= s; t.y *= s; t.z *= s; t.w *= s;
        *p = t;
    }
    __syncthreads();

    // 64x64 Gram partial over this code slice
    int a = tid >> 2;
    int bg = tid & 3;
    float acc[16];
#pragma unroll
    for (int i = 0; i < 16; i++) acc[i] = 0.f;
#pragma unroll 4
    for (int k = 0; k < 64; k++) {
        float va = nt[k * 68 + a];
        const float4* bp = (const float4*)(nt + k * 68 + bg * 16);
        float4 q0 = bp[0], q1 = bp[1], q2 = bp[2], q3 = bp[3];
        acc[0]  = fmaf(va, q0.x, acc[0]);  acc[1]  = fmaf(va, q0.y, acc[1]);
        acc[2]  = fmaf(va, q0.z, acc[2]);  acc[3]  = fmaf(va, q0.w, acc[3]);
        acc[4]  = fmaf(va, q1.x, acc[4]);  acc[5]  = fmaf(va, q1.y, acc[5]);
        acc[6]  = fmaf(va, q1.z, acc[6]);  acc[7]  = fmaf(va, q1.w, acc[7]);
        acc[8]  = fmaf(va, q2.x, acc[8]);  acc[9]  = fmaf(va, q2.y, acc[9]);
        acc[10] = fmaf(va, q2.z, acc[10]); acc[11] = fmaf(va, q2.w, acc[11]);
        acc[12] = fmaf(va, q3.x, acc[12]); acc[13] = fmaf(va, q3.y, acc[13]);
        acc[14] = fmaf(va, q3.z, acc[14]); acc[15] = fmaf(va, q3.w, acc[15]);
    }
    float* op = g_gram + a * 64 + bg * 16;
#pragma unroll
    for (int i = 0; i < 16; i++) atomicAdd(op + i, acc[i]);
}

// ---------------- main: mma.sync tf32 3-term GEMM, B straight from global, barrier-free mainloop ----------------
__global__ __launch_bounds__(256, 2)
void main_kernel(const float* __restrict__ x, const float* __restrict__ emb,
                 float* __restrict__ out, int N) {
    __shared__ float Rm[128], Rz[128], Rs[128];
    __shared__ int   RiA[128], idxRow[128];
    __shared__ float scr[256];
    __shared__ int   flg;

    const int tid  = threadIdx.x;
    const int warp = tid >> 5;
    const int lane = tid & 31;
    const int gid  = lane >> 2;   // 0..7
    const int t4   = lane & 3;    // 0..3
    const int r0   = blockIdx.x * 128;

    float* qout   = out;
    float* idxout = out + (size_t)N * DDIM + 5;

    // ---- load A fragments once: rows warp*16+gid (+8), tf32 hi/lo ----
    uint32_t a_hi[8][4], a_lo[8][4];
    {
        const float* p0 = x + (size_t)(r0 + warp * 16 + gid) * DDIM + t4;
        const float* p1 = p0 + 8 * DDIM;
#pragma unroll
        for (int kk = 0; kk < 8; kk++) {
            float xv[4] = { p0[kk * 8], p1[kk * 8], p0[kk * 8 + 4], p1[kk * 8 + 4] };
#pragma unroll
            for (int e = 0; e < 4; e++) {
                float hi = to_tf32(xv[e]);
                a_hi[kk][e] = __float_as_uint(hi);
                a_lo[kk][e] = __float_as_uint(to_tf32(xv[e] - hi));
            }
        }
    }

    float m0 = -1e30f, Z0 = 0.f, S0 = 0.f;
    float m1 = -1e30f, Z1 = 0.f, S1 = 0.f;
    int   b0i = 0, b1i = 0;

    // barrier-free mainloop: B quads straight from g_bq (L1-resident per tile)
    const float* bq_base = g_bq + (size_t)gid * 128 + t4 * 4;
    const float2* e2base = (const float2*)(g_en2) + t4;   // pair (2*t4, 2*t4+1)

    for (int t = 0; t < CTILES; t++) {
        const float* bqt = bq_base + (size_t)t * 64 * 128;
        const float2* e2t = e2base + t * 32;
#pragma unroll
        for (int ntl = 0; ntl < 8; ntl++) {
            float dA0 = 0.f, dA1 = 0.f, dA2 = 0.f, dA3 = 0.f;
            float dB0 = 0.f, dB1 = 0.f, dB2 = 0.f, dB3 = 0.f;
            const float* bp = bqt + ntl * 8 * 128;
#pragma unroll
            for (int kk = 0; kk < 8; kk++) {
                float4 f = __ldg((const float4*)(bp + kk * 16));
                uint32_t hx = __float_as_uint(f.x), hy = __float_as_uint(f.y);
                uint32_t lx = __float_as_uint(f.z), ly = __float_as_uint(f.w);
                if ((kk & 1) == 0) {
                    mma_tf32(dA0, dA1, dA2, dA3, a_hi[kk], hx, hy);
                    mma_tf32(dB0, dB1, dB2, dB3, a_hi[kk], lx, ly);
                    mma_tf32(dA0, dA1, dA2, dA3, a_lo[kk], hx, hy);
                } else {
                    mma_tf32(dB0, dB1, dB2, dB3, a_hi[kk], hx, hy);
                    mma_tf32(dA0, dA1, dA2, dA3, a_hi[kk], lx, ly);
                    mma_tf32(dB0, dB1, dB2, dB3, a_lo[kk], hx, hy);
                }
            }
            float d0 = dA0 + dB0, d1 = dA1 + dB1;
            float d2 = dA2 + dB2, d3 = dA3 + dB3;
            int col0 = t * 64 + ntl * 8 + 2 * t4;
            float2 e2 = __ldg(e2t + ntl * 4);
            float av0 = fmaf(2.f, d0, -e2.x), av1 = fmaf(2.f, d1, -e2.y);
            float av2 = fmaf(2.f, d2, -e2.x), av3 = fmaf(2.f, d3, -e2.y);
            UPD2(m0, Z0, S0, b0i, av0, av1, col0);
            UPD2(m1, Z1, S1, b1i, av2, av3, col0);
        }
    }

    // ---- merge the 4 column-threads of each row (shfl within quad) ----
#pragma unroll
    for (int off = 1; off <= 2; off <<= 1) {
        float m2 = __shfl_xor_sync(0xffffffffu, m0, off);
        float Z2 = __shfl_xor_sync(0xffffffffu, Z0, off);
        float S2 = __shfl_xor_sync(0xffffffffu, S0, off);
        int   b2 = __shfl_xor_sync(0xffffffffu, b0i, off);
        MERGE(m0, Z0, S0, b0i, m2, Z2, S2, b2);
        float m3 = __shfl_xor_sync(0xffffffffu, m1, off);
        float Z3 = __shfl_xor_sync(0xffffffffu, Z1, off);
        float S3 = __shfl_xor_sync(0xffffffffu, S1, off);
        int   b3 = __shfl_xor_sync(0xffffffffu, b1i, off);
        MERGE(m1, Z1, S1, b1i, m3, Z3, S3, b3);
    }
    if (t4 == 0) {
        int rowA = warp * 16 + gid;
        Rm[rowA] = m0; Rz[rowA] = Z0; Rs[rowA] = S0; RiA[rowA] = b0i;
        Rm[rowA + 8] = m1; Rz[rowA + 8] = Z1; Rs[rowA + 8] = S1; RiA[rowA + 8] = b1i;
    }
    __syncthreads();

    // ---- per-row entropy + index ----
    float H = 0.f;
    if (tid < 128) {
        float mm = Rm[tid], zz = Rz[tid], ss = Rs[tid];
        int ii = RiA[tid];
        H = mm + __logf(zz) - ss / zz;
        idxRow[tid] = ii;
        idxout[r0 + tid] = (float)ii;
        atomicAdd(&g_hist[ii], 1);
    }
    scr[tid] = (tid < 128) ? H : 0.f;
    __syncthreads();
    for (int s = 128; s > 0; s >>= 1) {
        if (tid < s) scr[tid] += scr[tid + s];
        __syncthreads();
    }
    if (tid == 0) g_pent[blockIdx.x] = scr[0];
    __syncthreads();

    // ---- gather quantized rows + commitment ----
    float ca = 0.f;
#pragma unroll
    for (int i = 0; i < 8; i++) {
        int v = tid + 256 * i;
        int row = v >> 4;
        int c4 = v & 15;
        int code = idxRow[row];
        float4 q  = ((const float4*)emb)[(size_t)code * 16 + c4];
        float4 xv = ((const float4*)x)[(size_t)(r0 + row) * 16 + c4];
        ((float4*)qout)[(size_t)(r0 + row) * 16 + c4] = q;
        float dx = q.x - xv.x, dy = q.y - xv.y, dz = q.z - xv.z, dw = q.w - xv.w;
        ca += dx * dx + dy * dy + dz * dz + dw * dw;
    }
    __syncthreads();
    scr[tid] = ca;
    __syncthreads();
    for (int s = 128; s > 0; s >>= 1) {
        if (tid < s) scr[tid] += scr[tid + s];
        __syncthreads();
    }
    if (tid == 0) g_pcommit[blockIdx.x] = scr[0];

    // ---- last-block finalize (also restores the zero-invariant) ----
    __threadfence();
    if (tid == 0) {
        int tk = atomicAdd(&g_done, 1);
        flg = (tk == NBLOCKS - 1) ? 1 : 0;
    }
    __syncthreads();
    if (flg) {
        __threadfence();
        float v = 0.f;
        for (int i = tid; i < NBLOCKS; i += 256) v += g_pcommit[i];
        scr[tid] = v;
        __syncthreads();
        for (int s = 128; s > 0; s >>= 1) { if (tid < s) scr[tid] += scr[tid + s]; __syncthreads(); }
        float commitSum = scr[0];
        __syncthreads();

        v = 0.f;
        for (int i = tid; i < NBLOCKS; i += 256) v += g_pent[i];
        scr[tid] = v;
        __syncthreads();
        for (int s = 128; s > 0; s >>= 1) { if (tid < s) scr[tid] += scr[tid + s]; __syncthreads(); }
        float entSum = scr[0];
        __syncthreads();

        v = 0.f;
        for (int e = tid; e < 4096; e += 256) {
            float g = g_gram[e];
            v = fmaf(g, g, v);
            g_gram[e] = 0.f;                       // restore invariant
        }
        scr[tid] = v;
        __syncthreads();
        for (int s = 128; s > 0; s >>= 1) { if (tid < s) scr[tid] += scr[tid + s]; __syncthreads(); }
        float orthoSum = scr[0];
        __syncthreads();

        v = 0.f;
        for (int i = tid; i < KCODES; i += 256) {
            float avg = (float)g_hist[i] / (float)N;
            v += avg * logf(avg + 1e-10f);
            g_hist[i] = 0;                         // restore invariant
        }
        scr[tid] = v;
        __syncthreads();
        for (int s = 128; s > 0; s >>= 1) { if (tid < s) scr[tid] += scr[tid + s]; __syncthreads(); }
        float psum = scr[0];

        if (tid == 0) {
            size_t Q = (size_t)N * DDIM;
            float nu = 0.f;
            for (int i = 0; i < 16; i++) nu += g_usedp[i];
            out[Q + 0] = commitSum / (float)Q;                 // commitment_loss
            out[Q + 1] = orthoSum / (nu * nu) - 1.f / nu;      // ortho_loss
            out[Q + 2] = entSum / ((float)N * 10.f);           // entropy_loss (/log2(1024))
            out[Q + 3] = expf(-psum);                          // perplexity
            out[Q + 4] = nu / (float)KCODES;                   // coverage
            g_done = 0;                                        // restore invariant
        }
    }
}

extern "C" void kernel_launch(void* const* d_in, const int* in_sizes, int n_in,
                              void* d_out, int out_size) {
    const float* x   = (const float*)d_in[0];   // [16,2048,64] fp32
    const float* emb = (const float*)d_in[1];   // [1024,64] fp32
    const float* cc  = (const float*)d_in[2];   // [1024] fp32
    int N = in_sizes[0] / DDIM;                 // 32768

    aux_kernel<<<16, 256>>>(emb, cc);
    main_kernel<<<NBLOCKS, 256>>>(x, emb, (float*)d_out, N);
}

// round 15
// speedup vs baseline: 1.4351x; 1.4351x over previous
#include <cuda_runtime.h>
#include <math.h>
#include <stdint.h>

#define KCODES 1024
#define DDIM   64
#define NBLOCKS 256       // 32768 rows / 128 rows per block
#define CTILES  16        // 1024 codes / 64 codes per tile

// B smem layout: quad [hi_k, hi_k+4, lo_k, lo_k+4] at Es[code*176 + kk*20 + t4*4]
#define KKSTRIDE 20
#define CSTRIDE  176

// dynamic smem layout (float offsets)
#define ES0_OFF   0
#define ES1_OFF   11264
#define EN0_OFF   22528
#define EN1_OFF   22592
#define RM_OFF    22656
#define RZ_OFF    22784
#define RS_OFF    22912
#define RI_OFF    23040
#define IDX_OFF   23168
#define SCR_OFF   23296
#define FLG_OFF   23552
#define SMEM_FLOATS 23556
#define SMEM_BYTES  (SMEM_FLOATS * 4)

// ---------------- device scratch (no allocation allowed) ----------------
// g_hist, g_gram, g_done rely on the zero-invariant: zero at module load,
// re-zeroed by finalize at the end of every run (graph-replay safe).
__device__ float g_en2[KCODES];
__device__ int   g_hist[KCODES];
__device__ float g_usedp[16];
__device__ float g_pcommit[NBLOCKS];
__device__ float g_pent[NBLOCKS];
__device__ float g_gram[4096];
__device__ int   g_done;

// ---------------- helpers ----------------
__device__ __forceinline__ float to_tf32(float v) {
    float r;
    asm("cvt.rna.tf32.f32 %0, %1;" : "=f"(r) : "f"(v));
    return r;
}

// D += A(row-major m16k8, tf32) * B(col-major k8n8, tf32), fp32 accum
__device__ __forceinline__ void mma_tf32(float& d0, float& d1, float& d2, float& d3,
                                         const uint32_t a[4], uint32_t b0, uint32_t b1) {
    asm("mma.sync.aligned.m16n8k8.row.col.f32.tf32.tf32.f32 "
        "{%0,%1,%2,%3}, {%4,%5,%6,%7}, {%8,%9}, {%0,%1,%2,%3};"
        : "+f"(d0), "+f"(d1), "+f"(d2), "+f"(d3)
        : "r"(a[0]), "r"(a[1]), "r"(a[2]), "r"(a[3]), "r"(b0), "r"(b1));
}

// batched online-softmax update for a pair of new logits
#define UPD2(mv, Zv, Sv, biv, av0, av1, col0) do {                            \
    float _q = fmaxf((av0), (av1));                                           \
    if (_q > (mv)) {                                                          \
        float _scl = __expf((mv) - _q);                                       \
        (Zv) *= _scl; (Sv) *= _scl;                                           \
        (mv) = _q;                                                            \
        (biv) = ((av0) >= (av1)) ? (col0) : (col0) + 1;                       \
    }                                                                         \
    float _p0 = __expf((av0) - (mv));                                         \
    float _p1 = __expf((av1) - (mv));                                         \
    (Zv) += _p0 + _p1;                                                        \
    (Sv) = fmaf((av0), _p0, fmaf((av1), _p1, (Sv)));                          \
} while (0)

#define MERGE(mv, Zv, Sv, biv, m2, Z2, S2, b2) do {                           \
    float _mm = fmaxf((mv), (m2));                                            \
    float _sA = __expf((mv) - _mm);                                           \
    float _sB = __expf((m2) - _mm);                                           \
    float _Zn = (Zv) * _sA + (Z2) * _sB;                                      \
    float _Sn = (Sv) * _sA + (S2) * _sB;                                      \
    if ((m2) > (mv) || ((m2) == (mv) && (b2) < (biv))) (biv) = (b2);          \
    (mv) = _mm; (Zv) = _Zn; (Sv) = _Sn; } while (0)

// ---------------- aux: en2 + used + ortho Gram partial (16 blocks x 256) ----------------
__global__ __launch_bounds__(256, 4)
void aux_kernel(const float* __restrict__ emb, const float* __restrict__ cc) {
    __shared__ float nt[64 * 68];
    __shared__ float scl[64];
    int tid = threadIdx.x;
    int k0 = blockIdx.x * 64;

#pragma unroll
    for (int i = 0; i < 4; i++) {
        int v = tid + 256 * i;
        int k = v >> 4, c4 = v & 15;
        *(float4*)(nt + k * 68 + c4 * 4) = ((const float4*)emb)[(size_t)(k0 + k) * 16 + c4];
    }
    __syncthreads();

    if (tid < 64) {
        float s = 0.f;
        const float* r = nt + tid * 68;
#pragma unroll 8
        for (int d = 0; d < 64; d++) s = fmaf(r[d], r[d], s);
        g_en2[k0 + tid] = s;
        float msk = (cc[k0 + tid] >= 1.f) ? 1.f : 0.f;
        scl[tid] = msk / fmaxf(sqrtf(s), 1e-12f);
    }
    __syncthreads();

    if (tid == 0) {
        float u = 0.f;
        for (int i = 0; i < 64; i++) u += (scl[i] > 0.f) ? 1.f : 0.f;
        g_usedp[blockIdx.x] = u;
    }

#pragma unroll
    for (int i = 0; i < 4; i++) {
        int v = tid + 256 * i;
        int k = v >> 4, c4 = v & 15;
        float4* p = (float4*)(nt + k * 68 + c4 * 4);
        float4 t = *p;
        float s = scl[k];
        t.x *= s; t.y *= s; t.z *= s; t.w *= s;
        *p = t;
    }
    __syncthreads();

    int a = tid >> 2;
    int bg = tid & 3;
    float acc[16];
#pragma unroll
    for (int i = 0; i < 16; i++) acc[i] = 0.f;
#pragma unroll 4
    for (int k = 0; k < 64; k++) {
        float va = nt[k * 68 + a];
        const float4* bp = (const float4*)(nt + k * 68 + bg * 16);
        float4 q0 = bp[0], q1 = bp[1], q2 = bp[2], q3 = bp[3];
        acc[0]  = fmaf(va, q0.x, acc[0]);  acc[1]  = fmaf(va, q0.y, acc[1]);
        acc[2]  = fmaf(va, q0.z, acc[2]);  acc[3]  = fmaf(va, q0.w, acc[3]);
        acc[4]  = fmaf(va, q1.x, acc[4]);  acc[5]  = fmaf(va, q1.y, acc[5]);
        acc[6]  = fmaf(va, q1.z, acc[6]);  acc[7]  = fmaf(va, q1.w, acc[7]);
        acc[8]  = fmaf(va, q2.x, acc[8]);  acc[9]  = fmaf(va, q2.y, acc[9]);
        acc[10] = fmaf(va, q2.z, acc[10]); acc[11] = fmaf(va, q2.w, acc[11]);
        acc[12] = fmaf(va, q3.x, acc[12]); acc[13] = fmaf(va, q3.y, acc[13]);
        acc[14] = fmaf(va, q3.z, acc[14]); acc[15] = fmaf(va, q3.w, acc[15]);
    }
    float* op = g_gram + a * 64 + bg * 16;
#pragma unroll
    for (int i = 0; i < 16; i++) atomicAdd(op + i, acc[i]);
}

// ---------------- main: mma.sync tf32 3-term split GEMM + fused softmax/argmax ----------------
// R13 base (double-buffered smem B) + deferred epilogue + kk-level LDS prefetch + 2x fold into A.
__global__ __launch_bounds__(256, 2)
void main_kernel(const float* __restrict__ x, const float* __restrict__ emb,
                 float* __restrict__ out, int N) {
    extern __shared__ float sm[];
    float* Rm     = sm + RM_OFF;
    float* Rz     = sm + RZ_OFF;
    float* Rs     = sm + RS_OFF;
    int*   RiA    = (int*)(sm + RI_OFF);
    int*   idxRow = (int*)(sm + IDX_OFF);
    float* scr    = sm + SCR_OFF;
    int*   flg    = (int*)(sm + FLG_OFF);

    const int tid  = threadIdx.x;
    const int warp = tid >> 5;
    const int lane = tid & 31;
    const int gid  = lane >> 2;   // 0..7
    const int t4   = lane & 3;    // 0..3
    const int r0   = blockIdx.x * 128;

    float* qout   = out;
    float* idxout = out + (size_t)N * DDIM + 5;

    // ---- load A fragments once: rows warp*16+gid (+8), 2x folded, tf32 hi/lo ----
    uint32_t a_hi[8][4], a_lo[8][4];
    {
        const float* p0 = x + (size_t)(r0 + warp * 16 + gid) * DDIM + t4;
        const float* p1 = p0 + 8 * DDIM;
#pragma unroll
        for (int kk = 0; kk < 8; kk++) {
            float xv[4] = { 2.f * p0[kk * 8], 2.f * p1[kk * 8],
                            2.f * p0[kk * 8 + 4], 2.f * p1[kk * 8 + 4] };
#pragma unroll
            for (int e = 0; e < 4; e++) {
                float hi = to_tf32(xv[e]);
                a_hi[kk][e] = __float_as_uint(hi);
                a_lo[kk][e] = __float_as_uint(to_tf32(xv[e] - hi));
            }
        }
    }

    float m0 = -1e30f, Z0 = 0.f, S0 = 0.f;
    float m1 = -1e30f, Z1 = 0.f, S1 = 0.f;
    int   b0i = 0, b1i = 0;

    // staging item: v in [0,512) -> (code = v>>3, kk = v&7); thread owns v = tid, tid+256.
    const int sc0 = tid >> 3, sk0 = tid & 7;
    const int sc1 = (tid + 256) >> 3, sk1 = (tid + 256) & 7;

    float4 pre[4];
    pre[0] = ((const float4*)emb)[(size_t)sc0 * 16 + sk0 * 2];
    pre[1] = ((const float4*)emb)[(size_t)sc0 * 16 + sk0 * 2 + 1];
    pre[2] = ((const float4*)emb)[(size_t)sc1 * 16 + sk1 * 2];
    pre[3] = ((const float4*)emb)[(size_t)sc1 * 16 + sk1 * 2 + 1];

    // stage tile 0 into buffer 0
#pragma unroll
    for (int i = 0; i < 2; i++) {
        float4 t0 = pre[2 * i], t1 = pre[2 * i + 1];
        int code = i ? sc1 : sc0, kk = i ? sk1 : sk0;
        float e[8] = { t0.x, t0.y, t0.z, t0.w, t1.x, t1.y, t1.z, t1.w };
        float hi[8], lo[8];
#pragma unroll
        for (int j = 0; j < 8; j++) { hi[j] = to_tf32(e[j]); lo[j] = to_tf32(e[j] - hi[j]); }
        float* base = sm + ES0_OFF + code * CSTRIDE + kk * KKSTRIDE;
#pragma unroll
        for (int q = 0; q < 4; q++)
            *(float4*)(base + q * 4) = make_float4(hi[q], hi[q + 4], lo[q], lo[q + 4]);
    }
    if (tid < 64) sm[EN0_OFF + tid] = g_en2[tid];
    // prefetch tile 1
    pre[0] = ((const float4*)emb)[(size_t)(64 + sc0) * 16 + sk0 * 2];
    pre[1] = ((const float4*)emb)[(size_t)(64 + sc0) * 16 + sk0 * 2 + 1];
    pre[2] = ((const float4*)emb)[(size_t)(64 + sc1) * 16 + sk1 * 2];
    pre[3] = ((const float4*)emb)[(size_t)(64 + sc1) * 16 + sk1 * 2 + 1];
    __syncthreads();

    // deferred-epilogue carry state
    float pd0 = 0.f, pd1 = 0.f, pd2 = 0.f, pd3 = 0.f, pe0 = 0.f, pe1 = 0.f;
    int   pcol = 0, pvalid = 0;

    for (int t = 0; t < CTILES; t++) {
        // stage tile t+1 into the other buffer (overlaps MMA of tile t below)
        if (t + 1 < CTILES) {
            float* Es1 = sm + (((t + 1) & 1) ? ES1_OFF : ES0_OFF);
            float* en1 = sm + (((t + 1) & 1) ? EN1_OFF : EN0_OFF);
#pragma unroll
            for (int i = 0; i < 2; i++) {
                float4 t0 = pre[2 * i], t1 = pre[2 * i + 1];
                int code = i ? sc1 : sc0, kk = i ? sk1 : sk0;
                float e[8] = { t0.x, t0.y, t0.z, t0.w, t1.x, t1.y, t1.z, t1.w };
                float hi[8], lo[8];
#pragma unroll
                for (int j = 0; j < 8; j++) { hi[j] = to_tf32(e[j]); lo[j] = to_tf32(e[j] - hi[j]); }
                float* base = Es1 + code * CSTRIDE + kk * KKSTRIDE;
#pragma unroll
                for (int q = 0; q < 4; q++)
                    *(float4*)(base + q * 4) = make_float4(hi[q], hi[q + 4], lo[q], lo[q + 4]);
            }
            if (tid < 64) en1[tid] = g_en2[(t + 1) * 64 + tid];
            // prefetch tile t+2
            if (t + 2 < CTILES) {
                int cb = (t + 2) * 64;
                pre[0] = ((const float4*)emb)[(size_t)(cb + sc0) * 16 + sk0 * 2];
                pre[1] = ((const float4*)emb)[(size_t)(cb + sc0) * 16 + sk0 * 2 + 1];
                pre[2] = ((const float4*)emb)[(size_t)(cb + sc1) * 16 + sk1 * 2];
                pre[3] = ((const float4*)emb)[(size_t)(cb + sc1) * 16 + sk1 * 2 + 1];
            }
        }

        // MMA + deferred epilogue on tile t (buffer t&1)
        const float* Es  = sm + ((t & 1) ? ES1_OFF : ES0_OFF);
        const float* ens = sm + ((t & 1) ? EN1_OFF : EN0_OFF);
#pragma unroll
        for (int ntl = 0; ntl < 8; ntl++) {
            float dA0 = 0.f, dA1 = 0.f, dA2 = 0.f, dA3 = 0.f;
            float dB0 = 0.f, dB1 = 0.f, dB2 = 0.f, dB3 = 0.f;
            const float* bp = Es + (ntl * 8 + gid) * CSTRIDE + t4 * 4;
            float4 f = *(const float4*)(bp);
#pragma unroll
            for (int kk = 0; kk < 8; kk++) {
                float4 fn = (kk < 7) ? *(const float4*)(bp + (kk + 1) * KKSTRIDE) : f;
                uint32_t hx = __float_as_uint(f.x), hy = __float_as_uint(f.y);
                uint32_t lx = __float_as_uint(f.z), ly = __float_as_uint(f.w);
                if ((kk & 1) == 0) {
                    mma_tf32(dA0, dA1, dA2, dA3, a_hi[kk], hx, hy);
                    mma_tf32(dB0, dB1, dB2, dB3, a_hi[kk], lx, ly);
                    mma_tf32(dA0, dA1, dA2, dA3, a_lo[kk], hx, hy);
                } else {
                    mma_tf32(dB0, dB1, dB2, dB3, a_hi[kk], hx, hy);
                    mma_tf32(dA0, dA1, dA2, dA3, a_hi[kk], lx, ly);
                    mma_tf32(dB0, dB1, dB2, dB3, a_lo[kk], hx, hy);
                }
                f = fn;
            }
            // run the PREVIOUS ntl's epilogue while this ntl's MMAs drain
            if (pvalid) {
                float av0 = pd0 - pe0, av1 = pd1 - pe1;
                float av2 = pd2 - pe0, av3 = pd3 - pe1;
                UPD2(m0, Z0, S0, b0i, av0, av1, pcol);
                UPD2(m1, Z1, S1, b1i, av2, av3, pcol);
            }
            pd0 = dA0 + dB0; pd1 = dA1 + dB1;
            pd2 = dA2 + dB2; pd3 = dA3 + dB3;
            pe0 = ens[ntl * 8 + 2 * t4];
            pe1 = ens[ntl * 8 + 2 * t4 + 1];
            pcol = t * 64 + ntl * 8 + 2 * t4;
            pvalid = 1;
        }
        __syncthreads();
    }
    // final deferred epilogue
    {
        float av0 = pd0 - pe0, av1 = pd1 - pe1;
        float av2 = pd2 - pe0, av3 = pd3 - pe1;
        UPD2(m0, Z0, S0, b0i, av0, av1, pcol);
        UPD2(m1, Z1, S1, b1i, av2, av3, pcol);
    }

    // ---- merge the 4 column-threads of each row (shfl within quad) ----
#pragma unroll
    for (int off = 1; off <= 2; off <<= 1) {
        float m2 = __shfl_xor_sync(0xffffffffu, m0, off);
        float Z2 = __shfl_xor_sync(0xffffffffu, Z0, off);
        float S2 = __shfl_xor_sync(0xffffffffu, S0, off);
        int   b2 = __shfl_xor_sync(0xffffffffu, b0i, off);
        MERGE(m0, Z0, S0, b0i, m2, Z2, S2, b2);
        float m3 = __shfl_xor_sync(0xffffffffu, m1, off);
        float Z3 = __shfl_xor_sync(0xffffffffu, Z1, off);
        float S3 = __shfl_xor_sync(0xffffffffu, S1, off);
        int   b3 = __shfl_xor_sync(0xffffffffu, b1i, off);
        MERGE(m1, Z1, S1, b1i, m3, Z3, S3, b3);
    }
    if (t4 == 0) {
        int rowA = warp * 16 + gid;
        Rm[rowA] = m0; Rz[rowA] = Z0; Rs[rowA] = S0; RiA[rowA] = b0i;
        Rm[rowA + 8] = m1; Rz[rowA + 8] = Z1; Rs[rowA + 8] = S1; RiA[rowA + 8] = b1i;
    }
    __syncthreads();

    // ---- per-row entropy + index ----
    float H = 0.f;
    if (tid < 128) {
        float mm = Rm[tid], zz = Rz[tid], ss = Rs[tid];
        int ii = RiA[tid];
        H = mm + __logf(zz) - ss / zz;
        idxRow[tid] = ii;
        idxout[r0 + tid] = (float)ii;
        atomicAdd(&g_hist[ii], 1);
    }
    scr[tid] = (tid < 128) ? H : 0.f;
    __syncthreads();
    for (int s = 128; s > 0; s >>= 1) {
        if (tid < s) scr[tid] += scr[tid + s];
        __syncthreads();
    }
    if (tid == 0) g_pent[blockIdx.x] = scr[0];
    __syncthreads();

    // ---- gather quantized rows + commitment ----
    float ca = 0.f;
#pragma unroll
    for (int i = 0; i < 8; i++) {
        int v = tid + 256 * i;
        int row = v >> 4;
        int c4 = v & 15;
        int code = idxRow[row];
        float4 q  = ((const float4*)emb)[(size_t)code * 16 + c4];
        float4 xv = ((const float4*)x)[(size_t)(r0 + row) * 16 + c4];
        ((float4*)qout)[(size_t)(r0 + row) * 16 + c4] = q;
        float dx = q.x - xv.x, dy = q.y - xv.y, dz = q.z - xv.z, dw = q.w - xv.w;
        ca += dx * dx + dy * dy + dz * dz + dw * dw;
    }
    __syncthreads();
    scr[tid] = ca;
    __syncthreads();
    for (int s = 128; s > 0; s >>= 1) {
        if (tid < s) scr[tid] += scr[tid + s];
        __syncthreads();
    }
    if (tid == 0) g_pcommit[blockIdx.x] = scr[0];

    // ---- last-block finalize (also restores the zero-invariant) ----
    __threadfence();
    if (tid == 0) {
        int tk = atomicAdd(&g_done, 1);
        *flg = (tk == NBLOCKS - 1) ? 1 : 0;
    }
    __syncthreads();
    if (*flg) {
        __threadfence();
        float v = 0.f;
        for (int i = tid; i < NBLOCKS; i += 256) v += g_pcommit[i];
        scr[tid] = v;
        __syncthreads();
        for (int s = 128; s > 0; s >>= 1) { if (tid < s) scr[tid] += scr[tid + s]; __syncthreads(); }
        float commitSum = scr[0];
        __syncthreads();

        v = 0.f;
        for (int i = tid; i < NBLOCKS; i += 256) v += g_pent[i];
        scr[tid] = v;
        __syncthreads();
        for (int s = 128; s > 0; s >>= 1) { if (tid < s) scr[tid] += scr[tid + s]; __syncthreads(); }
        float entSum = scr[0];
        __syncthreads();

        v = 0.f;
        for (int e = tid; e < 4096; e += 256) {
            float g = g_gram[e];
            v = fmaf(g, g, v);
            g_gram[e] = 0.f;                       // restore invariant
        }
        scr[tid] = v;
        __syncthreads();
        for (int s = 128; s > 0; s >>= 1) { if (tid < s) scr[tid] += scr[tid + s]; __syncthreads(); }
        float orthoSum = scr[0];
        __syncthreads();

        v = 0.f;
        for (int i = tid; i < KCODES; i += 256) {
            float avg = (float)g_hist[i] / (float)N;
            v += avg * logf(avg + 1e-10f);
            g_hist[i] = 0;                         // restore invariant
        }
        scr[tid] = v;
        __syncthreads();
        for (int s = 128; s > 0; s >>= 1) { if (tid < s) scr[tid] += scr[tid + s]; __syncthreads(); }
        float psum = scr[0];

        if (tid == 0) {
            size_t Q = (size_t)N * DDIM;
            float nu = 0.f;
            for (int i = 0; i < 16; i++) nu += g_usedp[i];
            out[Q + 0] = commitSum / (float)Q;                 // commitment_loss
            out[Q + 1] = orthoSum / (nu * nu) - 1.f / nu;      // ortho_loss
            out[Q + 2] = entSum / ((float)N * 10.f);           // entropy_loss (/log2(1024))
            out[Q + 3] = expf(-psum);                          // perplexity
            out[Q + 4] = nu / (float)KCODES;                   // coverage
            g_done = 0;                                        // restore invariant
        }
    }
}

extern "C" void kernel_launch(void* const* d_in, const int* in_sizes, int n_in,
                              void* d_out, int out_size) {
    const float* x   = (const float*)d_in[0];   // [16,2048,64] fp32
    const float* emb = (const float*)d_in[1];   // [1024,64] fp32
    const float* cc  = (const float*)d_in[2];   // [1024] fp32
    int N = in_sizes[0] / DDIM;                 // 32768

    cudaFuncSetAttribute(main_kernel, cudaFuncAttributeMaxDynamicSharedMemorySize, SMEM_BYTES);

    aux_kernel<<<16, 256>>>(emb, cc);
    main_kernel<<<NBLOCKS, 256, SMEM_BYTES>>>(x, emb, (float*)d_out, N);
}